// round 16
// baseline (speedup 1.0000x reference)
#include <cuda_runtime.h>

// TT-embedding — single persistent kernel, two m-half passes per token.
//   core0: (1,8,40,16)    A[x][p][b]     idx = x*640 + p*16 + b
//   core1: (16,8,32,16)   M[b][y][q][c]  idx = b*4096 + y*512 + q*16 + c
//   core2: (16,16,25,1)   C[c][z][r]     idx = c*400 + z*25 + r
//   id -> p = id/800, q = (id%800)/25, r = id%25
//   out[tok][(m*8+a)*16+z] = sum_c s[pq][c][a*8+m] * c2t[r][c][z]
//
// Phase A: smem c2t Cs[r][c][z]; build permuted s rows g_s[pq][c][a*8+m].
// Grid barrier (epoch tickets, monotonic -> graph-replay safe).
// Phase B: ONE warp per token, lane (a=lane>>2, zq=lane&3), TWO passes over
//   m-halves (h=0: m0..3, h=1: m4..7). Acc = 8 f32x2 (16 regs) per pass ->
//   ~45 live regs -> 4 blocks/SM (32 warps). Pass-2 s loads hit the same
//   32B sectors pass-1 fetched -> L1 hits. Stores fully coalesced.
//
// GRID=592 = 148 SMs x 4; __launch_bounds__(256,4): regs<=64,
// smem ~34KB x 4 = 137KB <= 228KB -> co-resident, barrier cannot deadlock.

#define NTOK  16384
#define GRID  592
#define NW    (GRID * 8)
#define NROWS 1280
typedef unsigned long long ull;

__device__ float g_s[NROWS * 1024];
__device__ unsigned g_bar;   // monotonic epoch counter (never reset)

__global__ __launch_bounds__(256, 4) void tt_fused(const float* __restrict__ c0,
                                                   const float* __restrict__ c1,
                                                   const float* __restrict__ c2,
                                                   const int* __restrict__ ids,
                                                   float* __restrict__ out) {
    __shared__ __align__(16) float Cs[6400];   // c2t [r][c][z]
    __shared__ float sA[128];                  // [x][b]
    __shared__ float sM[2048];                 // [b][y][c]
    __shared__ int sIds64;

    int t = threadIdx.x;
    int bid = blockIdx.x;

    // ---- Phase A0: c2 transpose into this block's smem ----
    for (int i = t; i < 6400; i += 256) {
        int r = i >> 8, cz = i & 255;
        int cc = cz >> 4, z = cz & 15;
        Cs[i] = c2[cc * 400 + z * 25 + r];
    }
    if (t == 0) {
        int ored = 0;
#pragma unroll
        for (int i = 0; i < 32; ++i) ored |= ids[2 * i + 1];
        sIds64 = (ored == 0) ? 1 : 0;
    }

    // ---- Phase A1: build this block's s rows (permuted layout) ----
    for (int pq = bid; pq < NROWS; pq += GRID) {
        int p = pq >> 5, q = pq & 31;
        __syncthreads();
        if (t < 128) {
            int x = t >> 4, b = t & 15;
            sA[t] = c0[x * 640 + p * 16 + b];
        }
        for (int i = t; i < 2048; i += 256) {
            int b = i >> 7, y = (i >> 4) & 7, cc = i & 15;
            sM[i] = c1[b * 4096 + y * 512 + q * 16 + cc];
        }
        __syncthreads();
        for (int o = t; o < 1024; o += 256) {
            int cc = o >> 6, xy = o & 63;
            int x = xy >> 3, y = xy & 7;
            float acc = 0.f;
#pragma unroll
            for (int b = 0; b < 16; ++b)
                acc += sA[x * 16 + b] * sM[b * 128 + y * 16 + cc];
            g_s[pq * 1024 + cc * 64 + ((xy & 7) << 3) + (xy >> 3)] = acc;
        }
    }

    int ids64 = sIds64;

    // ---- grid-wide barrier (epoch tickets; replay-safe) ----
    __threadfence();
    __syncthreads();
    if (t == 0) {
        unsigned k = atomicAdd(&g_bar, 1u);
        unsigned target = (k / GRID + 1u) * GRID;
        while (atomicAdd(&g_bar, 0u) < target) __nanosleep(32);
    }
    __syncthreads();
    __threadfence();

    // ---- Phase B: gather, 1 warp/token, two m-half passes ----
    int lane = t & 31, warp = t >> 5;
    int a = lane >> 2, zq = lane & 3;

    for (int tok = bid * 8 + warp; tok < NTOK; tok += NW) {
        int id = ids64 ? __ldg(ids + 2 * tok) : __ldg(ids + tok);
        int p = id / 800;
        int rem = id - p * 800;
        int q = rem / 25;
        int r = rem - q * 25;

        const float4* sp = reinterpret_cast<const float4*>(
            g_s + (p * 32 + q) * 1024 + a * 8);          // [c*16 + h]
        const ulonglong2* cr =
            reinterpret_cast<const ulonglong2*>(Cs + r * 256 + zq * 4);
        float* ob = out + (size_t)tok * 1024 + lane * 4;

#pragma unroll
        for (int h = 0; h < 2; ++h) {   // m-half pass
            ull acc0[4], acc1[4];       // [k: m=4h+k], z pairs
#pragma unroll
            for (int k = 0; k < 4; ++k) { acc0[k] = 0ull; acc1[k] = 0ull; }

#pragma unroll
            for (int c = 0; c < 16; ++c) {
                float4 sv = sp[c * 16 + h];   // m = 4h..4h+3 (pass-2: L1 hit)
                ulonglong2 cv = cr[c * 4];    // lane's 16B of c2t[r][c]

                ull b0, b1, b2, b3;
                asm("mov.b64 %0,{%1,%1};" : "=l"(b0) : "f"(sv.x));
                asm("mov.b64 %0,{%1,%1};" : "=l"(b1) : "f"(sv.y));
                asm("mov.b64 %0,{%1,%1};" : "=l"(b2) : "f"(sv.z));
                asm("mov.b64 %0,{%1,%1};" : "=l"(b3) : "f"(sv.w));

                asm("fma.rn.f32x2 %0,%1,%2,%0;" : "+l"(acc0[0]) : "l"(b0), "l"(cv.x));
                asm("fma.rn.f32x2 %0,%1,%2,%0;" : "+l"(acc1[0]) : "l"(b0), "l"(cv.y));
                asm("fma.rn.f32x2 %0,%1,%2,%0;" : "+l"(acc0[1]) : "l"(b1), "l"(cv.x));
                asm("fma.rn.f32x2 %0,%1,%2,%0;" : "+l"(acc1[1]) : "l"(b1), "l"(cv.y));
                asm("fma.rn.f32x2 %0,%1,%2,%0;" : "+l"(acc0[2]) : "l"(b2), "l"(cv.x));
                asm("fma.rn.f32x2 %0,%1,%2,%0;" : "+l"(acc1[2]) : "l"(b2), "l"(cv.y));
                asm("fma.rn.f32x2 %0,%1,%2,%0;" : "+l"(acc0[3]) : "l"(b3), "l"(cv.x));
                asm("fma.rn.f32x2 %0,%1,%2,%0;" : "+l"(acc1[3]) : "l"(b3), "l"(cv.y));
            }

            // store m rows 4h..4h+3: addr = tok*1024 + h*512 + k*128 + lane*4
#pragma unroll
            for (int k = 0; k < 4; ++k)
                *reinterpret_cast<ulonglong2*>(ob + h * 512 + k * 128) =
                    make_ulonglong2(acc0[k], acc1[k]);
        }
    }
}

// ---------------------------------------------------------------------------
extern "C" void kernel_launch(void* const* d_in, const int* in_sizes, int n_in,
                              void* d_out, int out_size) {
    const float* core0 = (const float*)d_in[0];
    const float* core1 = (const float*)d_in[1];
    const float* core2 = (const float*)d_in[2];
    const int*   ids   = (const int*)d_in[3];
    float* out = (float*)d_out;

    tt_fused<<<GRID, 256>>>(core0, core1, core2, ids, out);
}

// round 17
// speedup vs baseline: 2.4369x; 2.4369x over previous
#include <cuda_runtime.h>

// TT-embedding — persistent kernel, cp.async double-buffered gather.
//   core0: (1,8,40,16)    A[x][p][b]     idx = x*640 + p*16 + b
//   core1: (16,8,32,16)   M[b][y][q][c]  idx = b*4096 + y*512 + q*16 + c
//   core2: (16,16,25,1)   C[c][z][r]     idx = c*400 + z*25 + r
//   id -> pq = id/25 (p=id/800,q=(id%800)/25), r = id%25
//   out[tok][(m*8+a)*16+z] = sum_c s[pq][c][a*8+m] * c2t[r][c][z]
//
// Phase A: dyn-smem Cs[r][c][z]; build permuted s rows g_s[pq][c][a*8+m].
// Grid barrier (epoch tickets, monotonic -> graph-replay safe).
// Phase B: groups of 8 tokens/block. cp.async.cg stages group i+1's s rows
//   (32KB) into buf[(i+1)&1] while computing group i from buf[i&1] —
//   gathered-row L2 latency hidden by the pipeline, not by registers.
//   Compute: 1 warp/token, lane (a=lane>>2, zq=lane&3); m-PAIR f32x2 accs
//   (s LDS pairs are native FMA2 operands), z dup'd by 4 ALU movs/c.
//
// GRID=296 = 148 x 2; launch_bounds(256,2): regs<=128 (no spill), dynamic
// smem 97.5KB x 2 = 195KB <= 228KB -> co-resident, barrier safe.
// cudaFuncSetAttribute is a host-side attribute set (not a stream op, not
// an allocation) -> graph-capture legal.

#define NTOK   16384
#define GRID   296
#define NROWS  1280
#define NGROUP 2048                 // NTOK/8
#define NITER  7                    // ceil(NGROUP/GRID)
typedef unsigned long long ull;

#define SM_CS   0                   // 6400 floats
#define SM_A    6400                // 128
#define SM_M    6528                // 2048
#define SM_BUF  8576                // 2 * 8192 floats (2 x 32KB)
#define SMEM_FLOATS (8576 + 16384)
#define SMEM_BYTES  (SMEM_FLOATS * 4)

__device__ float g_s[NROWS * 1024];
__device__ unsigned g_bar;          // monotonic epoch counter (never reset)

__global__ __launch_bounds__(256, 2) void tt_fused(const float* __restrict__ c0,
                                                   const float* __restrict__ c1,
                                                   const float* __restrict__ c2,
                                                   const int* __restrict__ ids,
                                                   float* __restrict__ out) {
    extern __shared__ __align__(16) float sm[];
    float* Cs = sm + SM_CS;
    float* sA = sm + SM_A;
    float* sM = sm + SM_M;
    float* sBuf = sm + SM_BUF;
    __shared__ int sIds64;

    int t = threadIdx.x;
    int bid = blockIdx.x;

    // ---- Phase A0: c2 transpose into smem ----
    for (int i = t; i < 6400; i += 256) {
        int r = i >> 8, cz = i & 255;
        int cc = cz >> 4, z = cz & 15;
        Cs[i] = c2[cc * 400 + z * 25 + r];
    }
    if (t == 0) {
        int ored = 0;
#pragma unroll
        for (int i = 0; i < 32; ++i) ored |= ids[2 * i + 1];
        sIds64 = (ored == 0) ? 1 : 0;
    }

    // ---- Phase A1: build this block's s rows (permuted layout) ----
    for (int pq = bid; pq < NROWS; pq += GRID) {
        int p = pq >> 5, q = pq & 31;
        __syncthreads();
        if (t < 128) {
            int x = t >> 4, b = t & 15;
            sA[t] = c0[x * 640 + p * 16 + b];
        }
        for (int i = t; i < 2048; i += 256) {
            int b = i >> 7, y = (i >> 4) & 7, cc = i & 15;
            sM[i] = c1[b * 4096 + y * 512 + q * 16 + cc];
        }
        __syncthreads();
        for (int o = t; o < 1024; o += 256) {
            int cc = o >> 6, xy = o & 63;
            int x = xy >> 3, y = xy & 7;
            float acc = 0.f;
#pragma unroll
            for (int b = 0; b < 16; ++b)
                acc += sA[x * 16 + b] * sM[b * 128 + y * 16 + cc];
            g_s[pq * 1024 + cc * 64 + ((xy & 7) << 3) + (xy >> 3)] = acc;
        }
    }

    // ---- grid-wide barrier (epoch tickets; replay-safe) ----
    __threadfence();
    __syncthreads();
    if (t == 0) {
        unsigned k = atomicAdd(&g_bar, 1u);
        unsigned target = (k / GRID + 1u) * GRID;
        while (atomicAdd(&g_bar, 0u) < target) __nanosleep(32);
    }
    __syncthreads();

    int ids64 = sIds64;
    int lane = t & 31, warp = t >> 5;
    int a = lane >> 2, zq = lane & 3;

    unsigned sbase = (unsigned)__cvta_generic_to_shared(sBuf);

    // ---- Phase B: double-buffered gather ----
    // stage(g -> buf b): 32 threads/token, each copies 8x16B of the s row.
    // cp.async.cg reads via L2 (coherent with the fenced g_s writes).
    int stl = t >> 5;                  // token-local 0..7 for staging
    int soff = (t & 31) * 4;           // float offset within row chunk

#define STAGE(g, b)                                                          \
    {                                                                        \
        int tok_ = (g) * 8 + stl;                                            \
        if (tok_ < NTOK) {                                                   \
            int id_ = ids64 ? __ldg(ids + 2 * tok_) : __ldg(ids + tok_);     \
            const float* src_ = g_s + (id_ / 25) * 1024 + soff;              \
            unsigned dst_ = sbase + (b) * 32768u + stl * 4096u +             \
                            (t & 31) * 16u;                                  \
            _Pragma("unroll")                                                \
            for (int k_ = 0; k_ < 8; ++k_)                                   \
                asm volatile(                                                \
                    "cp.async.cg.shared.global [%0], [%1], 16;" ::           \
                    "r"(dst_ + k_ * 512u), "l"(src_ + k_ * 128));            \
        }                                                                    \
        asm volatile("cp.async.commit_group;");                              \
    }

    STAGE(bid, 0)   // prologue: group for i=0

    for (int i = 0; i < NITER; ++i) {
        int gcur = i * GRID + bid;
        if (i + 1 < NITER) {
            STAGE((i + 1) * GRID + bid, (i + 1) & 1)
        } else {
            asm volatile("cp.async.commit_group;");
        }
        asm volatile("cp.async.wait_group 1;");
        __syncthreads();

        int tok = gcur * 8 + warp;
        if (tok < NTOK) {
            int id = ids64 ? __ldg(ids + 2 * tok) : __ldg(ids + tok);
            int r = id % 25;

            const float* sb = sBuf + (i & 1) * 8192 + warp * 1024 + a * 8;
            const float* cz = Cs + r * 256 + zq * 4;

            ull acc[4][4];   // [z within quad][m-pair]
#pragma unroll
            for (int zz = 0; zz < 4; ++zz)
#pragma unroll
                for (int mp = 0; mp < 4; ++mp) acc[zz][mp] = 0ull;

#pragma unroll
            for (int c = 0; c < 16; ++c) {
                ulonglong2 sv = *reinterpret_cast<const ulonglong2*>(sb + c * 64);
                ulonglong2 sw = *reinterpret_cast<const ulonglong2*>(sb + c * 64 + 4);
                float4 cv = *reinterpret_cast<const float4*>(cz + c * 16);

                ull d0, d1, d2, d3;
                asm("mov.b64 %0,{%1,%1};" : "=l"(d0) : "f"(cv.x));
                asm("mov.b64 %0,{%1,%1};" : "=l"(d1) : "f"(cv.y));
                asm("mov.b64 %0,{%1,%1};" : "=l"(d2) : "f"(cv.z));
                asm("mov.b64 %0,{%1,%1};" : "=l"(d3) : "f"(cv.w));

                asm("fma.rn.f32x2 %0,%1,%2,%0;" : "+l"(acc[0][0]) : "l"(sv.x), "l"(d0));
                asm("fma.rn.f32x2 %0,%1,%2,%0;" : "+l"(acc[0][1]) : "l"(sv.y), "l"(d0));
                asm("fma.rn.f32x2 %0,%1,%2,%0;" : "+l"(acc[0][2]) : "l"(sw.x), "l"(d0));
                asm("fma.rn.f32x2 %0,%1,%2,%0;" : "+l"(acc[0][3]) : "l"(sw.y), "l"(d0));
                asm("fma.rn.f32x2 %0,%1,%2,%0;" : "+l"(acc[1][0]) : "l"(sv.x), "l"(d1));
                asm("fma.rn.f32x2 %0,%1,%2,%0;" : "+l"(acc[1][1]) : "l"(sv.y), "l"(d1));
                asm("fma.rn.f32x2 %0,%1,%2,%0;" : "+l"(acc[1][2]) : "l"(sw.x), "l"(d1));
                asm("fma.rn.f32x2 %0,%1,%2,%0;" : "+l"(acc[1][3]) : "l"(sw.y), "l"(d1));
                asm("fma.rn.f32x2 %0,%1,%2,%0;" : "+l"(acc[2][0]) : "l"(sv.x), "l"(d2));
                asm("fma.rn.f32x2 %0,%1,%2,%0;" : "+l"(acc[2][1]) : "l"(sv.y), "l"(d2));
                asm("fma.rn.f32x2 %0,%1,%2,%0;" : "+l"(acc[2][2]) : "l"(sw.x), "l"(d2));
                asm("fma.rn.f32x2 %0,%1,%2,%0;" : "+l"(acc[2][3]) : "l"(sw.y), "l"(d2));
                asm("fma.rn.f32x2 %0,%1,%2,%0;" : "+l"(acc[3][0]) : "l"(sv.x), "l"(d3));
                asm("fma.rn.f32x2 %0,%1,%2,%0;" : "+l"(acc[3][1]) : "l"(sv.y), "l"(d3));
                asm("fma.rn.f32x2 %0,%1,%2,%0;" : "+l"(acc[3][2]) : "l"(sw.x), "l"(d3));
                asm("fma.rn.f32x2 %0,%1,%2,%0;" : "+l"(acc[3][3]) : "l"(sw.y), "l"(d3));
            }

            // epilogue: transpose m-pairs to z-major rows, coalesced stores
            float* ob = out + (size_t)tok * 1024 + a * 16 + zq * 4;
#pragma unroll
            for (int mp = 0; mp < 4; ++mp) {
                float l0, h0, l1, h1, l2, h2, l3, h3;
                asm("mov.b64 {%0,%1},%2;" : "=f"(l0), "=f"(h0) : "l"(acc[0][mp]));
                asm("mov.b64 {%0,%1},%2;" : "=f"(l1), "=f"(h1) : "l"(acc[1][mp]));
                asm("mov.b64 {%0,%1},%2;" : "=f"(l2), "=f"(h2) : "l"(acc[2][mp]));
                asm("mov.b64 {%0,%1},%2;" : "=f"(l3), "=f"(h3) : "l"(acc[3][mp]));
                *reinterpret_cast<float4*>(ob + (2 * mp) * 128) =
                    make_float4(l0, l1, l2, l3);
                *reinterpret_cast<float4*>(ob + (2 * mp + 1) * 128) =
                    make_float4(h0, h1, h2, h3);
            }
        }
        __syncthreads();
    }
#undef STAGE
}

// ---------------------------------------------------------------------------
extern "C" void kernel_launch(void* const* d_in, const int* in_sizes, int n_in,
                              void* d_out, int out_size) {
    const float* core0 = (const float*)d_in[0];
    const float* core1 = (const float*)d_in[1];
    const float* core2 = (const float*)d_in[2];
    const int*   ids   = (const int*)d_in[3];
    float* out = (float*)d_out;

    cudaFuncSetAttribute(tt_fused, cudaFuncAttributeMaxDynamicSharedMemorySize,
                         SMEM_BYTES);
    tt_fused<<<GRID, 256, SMEM_BYTES>>>(core0, core1, core2, ids, out);
}